// round 4
// baseline (speedup 1.0000x reference)
#include <cuda_runtime.h>
#include <cuda_bf16.h>
#include <math.h>

#define NQ 512
#define DM 1024
#define NEL (NQ * DM)

__device__ float g_txt[NEL];
__device__ float g_img[NEL];
__device__ float g_Q[2][NEL];
__device__ float g_K[2][NEL];
__device__ float g_V[2][NEL];
__device__ float g_O[2][NEL];

// ---------------------------------------------------------------------------
// tf32 tensor-core GEMM:  C = A(512xK) @ W(1024xK)^T + bias (+ resid)
// BM=64, BN=64, BK=32, 128 threads (4 warps 2x2), warp tile 32x32.
// Double-buffered smem, register prefetch, ONE __syncthreads per K-iter.
// Batched over gridDim.z via GemmArgs.
// ---------------------------------------------------------------------------
struct GemmArgs {
    const float* A[6];
    const float* W[6];
    const float* bias[6];
    const float* resid[6];
    float*       C[6];
    int          K[6];
};

__device__ __forceinline__ unsigned f2tf32(float x) {
    unsigned u;
    asm("cvt.rna.tf32.f32 %0, %1;" : "=r"(u) : "f"(x));
    return u;
}
__device__ __forceinline__ uint4 cvt4(float4 v) {
    return make_uint4(f2tf32(v.x), f2tf32(v.y), f2tf32(v.z), f2tf32(v.w));
}

__global__ __launch_bounds__(128) void gemm_tf32_kernel(GemmArgs args) {
    const int z = blockIdx.z;
    const float* __restrict__ A     = args.A[z];
    const float* __restrict__ W     = args.W[z];
    const float* __restrict__ bias  = args.bias[z];
    const float* __restrict__ resid = args.resid[z];
    float* __restrict__ C           = args.C[z];
    const int K = args.K[z];

    const int m0 = blockIdx.y * 64;
    const int n0 = blockIdx.x * 64;

    // stride 36 words: fragment bank = (4g+tg) mod 32 -> conflict-free
    __shared__ unsigned As[2][64][36];
    __shared__ unsigned Ws[2][64][36];

    const int tid  = threadIdx.x;
    const int lane = tid & 31;
    const int wid  = tid >> 5;          // 0..3
    const int wm   = (wid & 1) * 32;
    const int wn   = (wid >> 1) * 32;
    const int g    = lane >> 2;         // 0..7
    const int tg   = lane & 3;          // 0..3

    // load mapping: 64 rows x 8 float4 = 512 float4 per tile; 4 per thread
    const int lrow = tid >> 1;          // base row pattern
    (void)lrow;

    float acc[2][4][4];
#pragma unroll
    for (int mt = 0; mt < 2; mt++)
#pragma unroll
        for (int nt = 0; nt < 4; nt++)
#pragma unroll
            for (int r = 0; r < 4; r++) acc[mt][nt][r] = 0.f;

    float4 pa[4], pw[4];
    const int T = K >> 5;

    // prologue: LDG tile 0, STS into buf 0
#pragma unroll
    for (int it = 0; it < 4; it++) {
        int f = tid + it * 128;         // 0..511
        int r = f >> 3, q = f & 7;
        pa[it] = *(const float4*)(A + (m0 + r) * K + q * 4);
        pw[it] = *(const float4*)(W + (n0 + r) * K + q * 4);
    }
#pragma unroll
    for (int it = 0; it < 4; it++) {
        int f = tid + it * 128;
        int r = f >> 3, q = f & 7;
        *(uint4*)(&As[0][r][q * 4]) = cvt4(pa[it]);
        *(uint4*)(&Ws[0][r][q * 4]) = cvt4(pw[it]);
    }
    __syncthreads();

    for (int t = 0; t < T; t++) {
        const int cur = t & 1;

        // prefetch next tile into registers (overlaps MMA below)
        if (t + 1 < T) {
            const int k0 = (t + 1) * 32;
#pragma unroll
            for (int it = 0; it < 4; it++) {
                int f = tid + it * 128;
                int r = f >> 3, q = f & 7;
                pa[it] = *(const float4*)(A + (m0 + r) * K + k0 + q * 4);
                pw[it] = *(const float4*)(W + (n0 + r) * K + k0 + q * 4);
            }
        }

        // MMA over 4 k8-steps on buffer `cur`
#pragma unroll
        for (int ks = 0; ks < 4; ks++) {
            const int kb = ks * 8;
            unsigned a[2][4], b[4][2];
#pragma unroll
            for (int mt = 0; mt < 2; mt++) {
                int row = wm + mt * 16 + g;
                a[mt][0] = As[cur][row][kb + tg];
                a[mt][1] = As[cur][row + 8][kb + tg];
                a[mt][2] = As[cur][row][kb + tg + 4];
                a[mt][3] = As[cur][row + 8][kb + tg + 4];
            }
#pragma unroll
            for (int nt = 0; nt < 4; nt++) {
                int n = wn + nt * 8 + g;
                b[nt][0] = Ws[cur][n][kb + tg];
                b[nt][1] = Ws[cur][n][kb + tg + 4];
            }
#pragma unroll
            for (int mt = 0; mt < 2; mt++)
#pragma unroll
                for (int nt = 0; nt < 4; nt++) {
                    asm volatile(
                        "mma.sync.aligned.m16n8k8.row.col.f32.tf32.tf32.f32 "
                        "{%0,%1,%2,%3}, {%4,%5,%6,%7}, {%8,%9}, {%0,%1,%2,%3};"
                        : "+f"(acc[mt][nt][0]), "+f"(acc[mt][nt][1]),
                          "+f"(acc[mt][nt][2]), "+f"(acc[mt][nt][3])
                        : "r"(a[mt][0]), "r"(a[mt][1]), "r"(a[mt][2]), "r"(a[mt][3]),
                          "r"(b[nt][0]), "r"(b[nt][1]));
                }
        }

        // store next tile into the other buffer; single barrier per iter
        if (t + 1 < T) {
            const int nxt = cur ^ 1;
#pragma unroll
            for (int it = 0; it < 4; it++) {
                int f = tid + it * 128;
                int r = f >> 3, q = f & 7;
                *(uint4*)(&As[nxt][r][q * 4]) = cvt4(pa[it]);
                *(uint4*)(&Ws[nxt][r][q * 4]) = cvt4(pw[it]);
            }
            __syncthreads();
        }
    }

    // epilogue: bias (+resid)
#pragma unroll
    for (int mt = 0; mt < 2; mt++) {
#pragma unroll
        for (int nt = 0; nt < 4; nt++) {
            int row0 = m0 + wm + mt * 16 + g;
            int col  = n0 + wn + nt * 8 + tg * 2;
            float b0 = bias[col], b1 = bias[col + 1];
            float2 v0 = make_float2(acc[mt][nt][0] + b0, acc[mt][nt][1] + b1);
            float2 v1 = make_float2(acc[mt][nt][2] + b0, acc[mt][nt][3] + b1);
            if (resid) {
                float2 r0 = *(const float2*)(resid + row0 * DM + col);
                float2 r1 = *(const float2*)(resid + (row0 + 8) * DM + col);
                v0.x += r0.x; v0.y += r0.y;
                v1.x += r1.x; v1.y += r1.y;
            }
            *(float2*)(C + row0 * DM + col)       = v0;
            *(float2*)(C + (row0 + 8) * DM + col) = v1;
        }
    }
}

// ---------------------------------------------------------------------------
// sliding-window attention: one warp per (query, head)
// ---------------------------------------------------------------------------
__global__ void swattn_kernel(const float* __restrict__ kb0, const float* __restrict__ vb0,
                              const float* __restrict__ kb1, const float* __restrict__ vb1) {
    const int a = blockIdx.y;
    const int i = blockIdx.x;
    const int h = threadIdx.x >> 5;
    const int lane = threadIdx.x & 31;

    const float* __restrict__ Q  = g_Q[a];
    const float* __restrict__ Kc = g_K[a];
    const float* __restrict__ Vc = g_V[a];
    const float* __restrict__ kb = a ? kb1 : kb0;
    const float* __restrict__ vb = a ? vb1 : vb0;

    __shared__ float sc[8][66];

    const float scale = 0.08838834764831845f;  // 1/sqrt(128)
    const int base = h * 128 + lane * 4;
    const float4 q4 = *(const float4*)(Q + i * DM + base);

    const int lo = i - 32;
    const int p_start = max(0, 32 - i);
    const int p_end   = min(66, 544 - i);
    const int invalid = 66 - (p_end - p_start);
    const int n_pad   = max(0, invalid - 2);

    for (int p = p_start; p < p_end; p++) {
        const float4 k4 = *(const float4*)(Kc + (lo + p) * DM + base);
        float part = q4.x * k4.x + q4.y * k4.y + q4.z * k4.z + q4.w * k4.w;
#pragma unroll
        for (int off = 16; off > 0; off >>= 1)
            part += __shfl_xor_sync(0xffffffffu, part, off);
        if (lane == 0) sc[h][p] = part * scale;
    }

    float s_pad = -1e30f;
    if (n_pad > 0) {
        const float4 kb4 = *(const float4*)(kb + base);
        float part = q4.x * kb4.x + q4.y * kb4.y + q4.z * kb4.z + q4.w * kb4.w;
#pragma unroll
        for (int off = 16; off > 0; off >>= 1)
            part += __shfl_xor_sync(0xffffffffu, part, off);
        s_pad = part * scale;
    }
    __syncwarp();

    float mloc = (n_pad > 0) ? s_pad : -1e30f;
    for (int p = p_start + lane; p < p_end; p += 32) mloc = fmaxf(mloc, sc[h][p]);
#pragma unroll
    for (int off = 16; off > 0; off >>= 1)
        mloc = fmaxf(mloc, __shfl_xor_sync(0xffffffffu, mloc, off));
    const float m = mloc;

    float dloc = 0.f;
    for (int p = p_start + lane; p < p_end; p += 32) {
        float e = expf(sc[h][p] - m);
        sc[h][p] = e;
        dloc += e;
    }
#pragma unroll
    for (int off = 16; off > 0; off >>= 1)
        dloc += __shfl_xor_sync(0xffffffffu, dloc, off);
    float w_pad = 0.f;
    if (n_pad > 0) w_pad = (float)n_pad * expf(s_pad - m);
    const float denom = dloc + w_pad;
    __syncwarp();

    float4 acc = make_float4(0.f, 0.f, 0.f, 0.f);
    for (int p = p_start; p < p_end; p++) {
        const float w = sc[h][p];
        const float4 v4 = *(const float4*)(Vc + (lo + p) * DM + base);
        acc.x += w * v4.x; acc.y += w * v4.y; acc.z += w * v4.z; acc.w += w * v4.w;
    }
    if (n_pad > 0) {
        const float4 vb4 = *(const float4*)(vb + base);
        acc.x += w_pad * vb4.x; acc.y += w_pad * vb4.y;
        acc.z += w_pad * vb4.z; acc.w += w_pad * vb4.w;
    }
    const float inv = 1.f / denom;
    *(float4*)(g_O[a] + i * DM + base) =
        make_float4(acc.x * inv, acc.y * inv, acc.z * inv, acc.w * inv);
}

// ---------------------------------------------------------------------------
extern "C" void kernel_launch(void* const* d_in, const int* in_sizes, int n_in,
                              void* d_out, int out_size) {
    (void)in_sizes; (void)n_in; (void)out_size;

    const float* images   = (const float*)d_in[0];
    const float* captions = (const float*)d_in[1];
    const float* tp_w = (const float*)d_in[3];
    const float* tp_b = (const float*)d_in[4];
    const float* ip_w = (const float*)d_in[5];
    const float* ip_b = (const float*)d_in[6];
    const float* ia[8]; for (int k = 0; k < 8; k++) ia[k] = (const float*)d_in[7 + k];
    const float* ta[8]; for (int k = 0; k < 8; k++) ta[k] = (const float*)d_in[15 + k];
    float* out = (float*)d_out;

    float *txt, *img, *Qb, *Kb, *Vb, *Ob;
    cudaGetSymbolAddress((void**)&txt, g_txt);
    cudaGetSymbolAddress((void**)&img, g_img);
    cudaGetSymbolAddress((void**)&Qb, g_Q);
    cudaGetSymbolAddress((void**)&Kb, g_K);
    cudaGetSymbolAddress((void**)&Vb, g_V);
    cudaGetSymbolAddress((void**)&Ob, g_O);

    const dim3 blk(128);
    const int GX = DM / 64;   // 16
    const int GY = NQ / 64;   // 8

    // ---- launch 1: both input projections (z=2) ----
    {
        GemmArgs ar{};
        ar.A[0] = captions; ar.W[0] = tp_w; ar.bias[0] = tp_b; ar.resid[0] = nullptr; ar.C[0] = txt; ar.K[0] = 768;
        ar.A[1] = images;   ar.W[1] = ip_w; ar.bias[1] = ip_b; ar.resid[1] = nullptr; ar.C[1] = img; ar.K[1] = 1024;
        gemm_tf32_kernel<<<dim3(GX, GY, 2), blk>>>(ar);
    }

    // ---- launch 2: all six QKV projections (z=6) ----
    {
        GemmArgs ar{};
        const float* Aarr[6]  = { img,  txt,  txt,  txt,  img,  img  };
        const float* Warr[6]  = { ia[0], ia[2], ia[4], ta[0], ta[2], ta[4] };
        const float* Barr[6]  = { ia[1], ia[3], ia[5], ta[1], ta[3], ta[5] };
        float*       Carr[6]  = { Qb, Kb, Vb, Qb + NEL, Kb + NEL, Vb + NEL };
        for (int s = 0; s < 6; s++) {
            ar.A[s] = Aarr[s]; ar.W[s] = Warr[s]; ar.bias[s] = Barr[s];
            ar.resid[s] = nullptr; ar.C[s] = Carr[s]; ar.K[s] = 1024;
        }
        gemm_tf32_kernel<<<dim3(GX, GY, 6), blk>>>(ar);
    }

    // ---- launch 3: sliding-window attention ----
    swattn_kernel<<<dim3(NQ, 2), 256>>>(ia[3], ia[5], ta[3], ta[5]);

    // ---- launch 4: both output projections + residual (z=2) ----
    {
        GemmArgs ar{};
        ar.A[0] = Ob;       ar.W[0] = ia[6]; ar.bias[0] = ia[7]; ar.resid[0] = img; ar.C[0] = out;       ar.K[0] = 1024;
        ar.A[1] = Ob + NEL; ar.W[1] = ta[6]; ar.bias[1] = ta[7]; ar.resid[1] = txt; ar.C[1] = out + NEL; ar.K[1] = 1024;
        gemm_tf32_kernel<<<dim3(GX, GY, 2), blk>>>(ar);
    }
}